// round 14
// baseline (speedup 1.0000x reference)
#include <cuda_runtime.h>
#include <cuda_bf16.h>

// Problem constants
#define Bx 4
#define Cx 3
#define Hx 224
#define Wx 224
#define Kx 196
#define Ex 768
#define HW (Hx * Wx)               // 50176
#define KC (Kx * Cx)               // 588
#define BK (Bx * Kx)               // 784

#define BPB 49                     // blocks per batch (R10 proven grid)
#define NBLK (Bx * BPB)            // 196
#define TA 256
#define PIX_PER_BLOCK (TA * 4)     // 1024; 49*1024 = HW exactly

#define ROWS_PER_BLOCK 4           // 49 blocks * 4 rows = 196 = Kx
#define NREP 2                     // flush replicas (halve L2 per-addr serialization)
#define ROW_F4 8                   // 128 B per (b,k) row (L2-slice spread)

// Replicated pooled sums; element 0 of each row = {c0,c1,c2,pad}.
// Zero at module load; phase 2 re-zeroes consumed rows each call.
__device__ float4 g_pool4[NREP * BK * ROW_F4];

// Per-batch sub-barriers: monotone epoch counters, 128 B apart. u64 -> no overflow.
__device__ unsigned long long g_bar[Bx * 16];

__device__ __forceinline__ void red_add_v4(float4* p, float x, float y, float z) {
    asm volatile("red.global.add.v4.f32 [%0], {%1, %2, %3, %4};"
                 :: "l"(p), "f"(x), "f"(y), "f"(z), "f"(0.0f) : "memory");
}

__device__ __forceinline__ float4 ldcg4(const float4* p) {
    float4 v;
    asm volatile("ld.global.cg.v4.f32 {%0,%1,%2,%3}, [%4];"
                 : "=f"(v.x), "=f"(v.y), "=f"(v.z), "=f"(v.w) : "l"(p));
    return v;
}

__global__ void __launch_bounds__(TA)
fused_kernel(const float* __restrict__ img,
             const int* __restrict__ seg,
             const float* __restrict__ Wmat,
             const float* __restrict__ bias,
             float* __restrict__ out) {
    __shared__ float s_pool[KC];

    const int tid = threadIdx.x;
    const int b   = blockIdx.x / BPB;
    const int j   = blockIdx.x % BPB;
    const int rep = j & 1;                 // 25 even / 24 odd: balanced

    // ---------------- Phase 1: segment-sum (R10 body, unchanged) ----------
    for (int i = tid; i < KC; i += TA) s_pool[i] = 0.0f;
    __syncthreads();

    const int p0 = j * PIX_PER_BLOCK + tid * 4;
    const float* img_b = img + (size_t)b * Cx * HW;
    const int*   seg_b = seg + (size_t)b * HW;

    int4   s  = *(const int4*)  (seg_b + p0);
    float4 v0 = *(const float4*)(img_b + p0);
    float4 v1 = *(const float4*)(img_b + p0 + HW);
    float4 v2 = *(const float4*)(img_b + p0 + 2 * HW);

    atomicAdd(&s_pool[s.x * Cx + 0], v0.x);
    atomicAdd(&s_pool[s.x * Cx + 1], v1.x);
    atomicAdd(&s_pool[s.x * Cx + 2], v2.x);
    atomicAdd(&s_pool[s.y * Cx + 0], v0.y);
    atomicAdd(&s_pool[s.y * Cx + 1], v1.y);
    atomicAdd(&s_pool[s.y * Cx + 2], v2.y);
    atomicAdd(&s_pool[s.z * Cx + 0], v0.z);
    atomicAdd(&s_pool[s.z * Cx + 1], v1.z);
    atomicAdd(&s_pool[s.z * Cx + 2], v2.z);
    atomicAdd(&s_pool[s.w * Cx + 0], v0.w);
    atomicAdd(&s_pool[s.w * Cx + 1], v1.w);
    atomicAdd(&s_pool[s.w * Cx + 2], v2.w);

    __syncthreads();

    // Flush: one fire-and-forget v4 RED per key, into this block's replica.
    if (tid < Kx) {
        float c0 = s_pool[tid * Cx + 0];
        float c1 = s_pool[tid * Cx + 1];
        float c2 = s_pool[tid * Cx + 2];
        red_add_v4(&g_pool4[((size_t)rep * BK + b * Kx + tid) * ROW_F4],
                   c0, c1, c2);
    }

    // Prefetch phase-2 operands as vectors (independent of the barrier).
    // Threads 0..191 each own 4 consecutive e-columns.
    float4 w0, w1, w2, bb;
    const int e0 = tid * 4;
    if (tid < Ex / 4) {
        w0 = *(const float4*)&Wmat[0 * Ex + e0];
        w1 = *(const float4*)&Wmat[1 * Ex + e0];
        w2 = *(const float4*)&Wmat[2 * Ex + e0];
        bb = *(const float4*)&bias[e0];
    }

    // ---------------- Per-batch sub-barrier (49 arrivals; R10 form) -------
    __threadfence();                       // REDs globally visible first
    if (tid == 0) {
        unsigned long long* bar = &g_bar[b * 16];
        unsigned long long old = atomicAdd(bar, 1ULL);
        unsigned long long target = (old / BPB + 1ULL) * BPB;
        while (*(volatile unsigned long long*)bar < target) { }
    }
    __syncthreads();
    // Phase-2 pooled reads use ld.global.cg (L2 is the coherence point).

    // ---------------- Phase 2: 4 rows, vectorized stores -------------------
    const float inv = 1.0f / (float)HW;
    const int bk0 = b * Kx + j * ROWS_PER_BLOCK;

    if (tid < Ex / 4) {
        // Issue all row loads up front (8 independent ldcg4 -> one L2 trip)
        float4 q[ROWS_PER_BLOCK][NREP];
#pragma unroll
        for (int r = 0; r < ROWS_PER_BLOCK; r++) {
#pragma unroll
            for (int rp = 0; rp < NREP; rp++) {
                q[r][rp] = ldcg4(&g_pool4[((size_t)rp * BK + bk0 + r) * ROW_F4]);
            }
        }

#pragma unroll
        for (int r = 0; r < ROWS_PER_BLOCK; r++) {
            const int bk = bk0 + r;
            float p0 = (q[r][0].x + q[r][1].x) * inv;
            float p1 = (q[r][0].y + q[r][1].y) * inv;
            float p2 = (q[r][0].z + q[r][1].z) * inv;

            float4 o;
            o.x = fmaf(p0, w0.x, fmaf(p1, w1.x, fmaf(p2, w2.x, bb.x)));
            o.y = fmaf(p0, w0.y, fmaf(p1, w1.y, fmaf(p2, w2.y, bb.y)));
            o.z = fmaf(p0, w0.z, fmaf(p1, w1.z, fmaf(p2, w2.z, bb.z)));
            o.w = fmaf(p0, w0.w, fmaf(p1, w1.w, fmaf(p2, w2.w, bb.w)));
            *(float4*)&out[(size_t)bk * Ex + e0] = o;
        }
    }

    // Restore the zero-invariant for both replicas of the consumed rows.
    __syncthreads();
    if (tid < ROWS_PER_BLOCK * NREP) {
        const int r  = tid >> 1;           // 0..3
        const int rp = tid & 1;
        g_pool4[((size_t)rp * BK + bk0 + r) * ROW_F4] =
            make_float4(0.f, 0.f, 0.f, 0.f);
    }
}

extern "C" void kernel_launch(void* const* d_in, const int* in_sizes, int n_in,
                              void* d_out, int out_size) {
    const float* img  = (const float*)d_in[0];
    const int*   seg  = (const int*)d_in[1];
    const float* Wmat = (const float*)d_in[2];
    const float* bias = (const float*)d_in[3];
    float* out = (float*)d_out;

    fused_kernel<<<NBLK, TA>>>(img, seg, Wmat, bias, out);
}